// round 6
// baseline (speedup 1.0000x reference)
#include <cuda_runtime.h>
#include <cuda_fp16.h>
#include <cstdint>

#define D_FEAT      64
#define N_NODES_MAX 100000
#define EPS         128           // edges per 16-thread group
#define SUBS        8             // groups per block
#define EPB         (EPS * SUBS)  // 1024 edges per block
#define MARGIN      128           // extension margin staged beyond the window
#define SWIN        (EPB + MARGIN)
#define THREADS     128

// Scratch (allocation-free per harness rules). Intermediate hop in fp16.
__device__ __half g_tmp[(size_t)N_NODES_MAX * D_FEAT];

// ---- per-dtype row load/store helpers (each d4-thread owns 4 features) ----
template <bool HALF>
__device__ __forceinline__ float4 ld_feat(const char* p) {
    if (HALF) {
        uint2 r = *reinterpret_cast<const uint2*>(p);
        float2 a = __half22float2(*reinterpret_cast<__half2*>(&r.x));
        float2 b = __half22float2(*reinterpret_cast<__half2*>(&r.y));
        return make_float4(a.x, a.y, b.x, b.y);
    } else {
        return *reinterpret_cast<const float4*>(p);
    }
}
template <bool HALF>
__device__ __forceinline__ void st_feat(char* p, float4 v) {
    if (HALF) {
        uint2 u;
        __half2 h0 = __float22half2_rn(make_float2(v.x, v.y));
        __half2 h1 = __float22half2_rn(make_float2(v.z, v.w));
        u.x = *reinterpret_cast<uint32_t*>(&h0);
        u.y = *reinterpret_cast<uint32_t*>(&h1);
        *reinterpret_cast<uint2*>(p) = u;
    } else {
        *reinterpret_cast<float4*>(p) = v;
    }
}

// Sorted-row SpMM with run ownership: a group owns every run whose FIRST edge
// lies in its EPS-edge window. Owned runs are finished by extending past the
// window end (smem margin, gmem fallback). Leading continuation runs are
// accumulated then DISCARDED (their owner is the previous group). All output
// writes are exclusive STGs: no atomics, no zero-init, no fixup pass.
template <bool SRC_H, bool DST_H>
__global__ void __launch_bounds__(THREADS)
spmm_kernel(const char* __restrict__ src,
            const int*  __restrict__ erow,
            const int*  __restrict__ ecol,
            const float* __restrict__ eval,
            char*       __restrict__ dst,
            int n_edges, int n_rows) {
    constexpr int SRC_RB = SRC_H ? 128 : 256;    // bytes per feature row
    constexpr int DST_RB = DST_H ? 128 : 256;
    constexpr int SRC_TB = SRC_H ? 8 : 16;       // bytes per thread per row
    constexpr int DST_TB = DST_H ? 8 : 16;

    __shared__ alignas(16) int   s_row[SWIN];
    __shared__ alignas(16) int   s_off[SWIN];    // col * SRC_RB
    __shared__ alignas(16) float s_val[SWIN];

    const int base = blockIdx.x * EPB;
    const int tid  = threadIdx.x;

    // Vectorized staging of window + margin; pad with last row, val = 0.
    for (int i = tid * 4; i < SWIN; i += THREADS * 4) {
        const int e = base + i;
        if (e + 3 < n_edges) {
            int4   r = *reinterpret_cast<const int4*>(erow + e);
            int4   c = *reinterpret_cast<const int4*>(ecol + e);
            float4 v = *reinterpret_cast<const float4*>(eval + e);
            c.x *= SRC_RB; c.y *= SRC_RB; c.z *= SRC_RB; c.w *= SRC_RB;
            *reinterpret_cast<int4*>(s_row + i)   = r;
            *reinterpret_cast<int4*>(s_off + i)   = c;
            *reinterpret_cast<float4*>(s_val + i) = v;
        } else {
            #pragma unroll
            for (int k = 0; k < 4; k++) {
                int ee   = e + k;
                int esrc = min(max(ee, 0), n_edges - 1);
                int in   = (ee < n_edges);
                s_row[i + k] = erow[esrc];
                s_off[i + k] = in ? ecol[esrc] * SRC_RB : 0;
                s_val[i + k] = in ? eval[esrc] : 0.f;
            }
        }
    }
    __syncthreads();

    const int d4   = tid & 15;
    const int sub  = tid >> 4;
    const int off  = sub * EPS;
    const int goff = base + off;
    const char* sp = src + d4 * SRC_TB;
    char*       dp = dst + d4 * DST_TB;
    const float4 z4 = make_float4(0.f, 0.f, 0.f, 0.f);

    if (goff >= n_edges) return;                 // fully-padded group

    const int first = s_row[off];
    const int prev  = (off > 0) ? s_row[off - 1]
                                : ((goff == 0) ? -1 : erow[goff - 1]);
    const bool continuation = (prev == first);

    // Leading gap rows (prev, first): no edges anywhere -> zeros.
    for (int rr = prev + 1; rr < first; rr++)
        st_feat<DST_H>(dp + (size_t)rr * DST_RB, z4);

    int    cur       = first;
    bool   first_run = true;
    float4 acc       = make_float4(0.f, 0.f, 0.f, 0.f);

    for (int ib = 0; ib < EPS; ib += 8) {
        const int4   ra = *reinterpret_cast<const int4*>(s_row + off + ib);
        const int4   rb = *reinterpret_cast<const int4*>(s_row + off + ib + 4);
        const int4   ca = *reinterpret_cast<const int4*>(s_off + off + ib);
        const int4   cb = *reinterpret_cast<const int4*>(s_off + off + ib + 4);
        const float4 va = *reinterpret_cast<const float4*>(s_val + off + ib);
        const float4 vb = *reinterpret_cast<const float4*>(s_val + off + ib + 4);

        // 8 gathers in flight (MLP = 8)
        const float4 g0 = ld_feat<SRC_H>(sp + ca.x);
        const float4 g1 = ld_feat<SRC_H>(sp + ca.y);
        const float4 g2 = ld_feat<SRC_H>(sp + ca.z);
        const float4 g3 = ld_feat<SRC_H>(sp + ca.w);
        const float4 g4 = ld_feat<SRC_H>(sp + cb.x);
        const float4 g5 = ld_feat<SRC_H>(sp + cb.y);
        const float4 g6 = ld_feat<SRC_H>(sp + cb.z);
        const float4 g7 = ld_feat<SRC_H>(sp + cb.w);

        #define STEP(R, V, G)                                                \
        do {                                                                 \
            if ((R) != cur) {                                                \
                if (!(first_run && continuation)) {                          \
                    st_feat<DST_H>(dp + (size_t)cur * DST_RB, acc);          \
                } /* else: leading continuation run -> previous group owns */\
                first_run = false;                                           \
                for (int rr = cur + 1; rr < (R); rr++)                       \
                    st_feat<DST_H>(dp + (size_t)rr * DST_RB, z4);            \
                acc = make_float4(0.f, 0.f, 0.f, 0.f);                       \
                cur = (R);                                                   \
            }                                                                \
            acc.x += (V) * (G).x;                                            \
            acc.y += (V) * (G).y;                                            \
            acc.z += (V) * (G).z;                                            \
            acc.w += (V) * (G).w;                                            \
        } while (0)

        STEP(ra.x, va.x, g0);
        STEP(ra.y, va.y, g1);
        STEP(ra.z, va.z, g2);
        STEP(ra.w, va.w, g3);
        STEP(rb.x, vb.x, g4);
        STEP(rb.y, vb.y, g5);
        STEP(rb.z, vb.z, g6);
        STEP(rb.w, vb.w, g7);
        #undef STEP
    }

    // Window ended inside one continuation run we don't own -> nothing to do.
    if (first_run && continuation) return;

    // Extend the final (owned) run past the window: 4-batched for MLP.
    int ge = goff + EPS;
    while (ge < n_edges) {
        int   r[4], o[4];
        float v[4];
        #pragma unroll
        for (int k = 0; k < 4; k++) {
            int gek = ge + k;
            if (gek < n_edges) {
                int li = gek - base;
                if (li < SWIN) {                 // staged margin (normal path)
                    r[k] = s_row[li]; o[k] = s_off[li]; v[k] = s_val[li];
                } else {                         // pathological long run
                    r[k] = erow[gek]; o[k] = ecol[gek] * SRC_RB; v[k] = eval[gek];
                }
            } else {
                r[k] = -1; o[k] = 0; v[k] = 0.f;
            }
        }
        // count of leading edges still in this run
        int cnt = 0;
        #pragma unroll
        for (int k = 0; k < 4; k++) cnt += (cnt == k && r[k] == cur) ? 1 : 0;

        // issue all 4 gathers (offsets are always valid node rows)
        const float4 e0 = ld_feat<SRC_H>(sp + o[0]);
        const float4 e1 = ld_feat<SRC_H>(sp + o[1]);
        const float4 e2 = ld_feat<SRC_H>(sp + o[2]);
        const float4 e3 = ld_feat<SRC_H>(sp + o[3]);

        if (cnt > 0) { acc.x += v[0]*e0.x; acc.y += v[0]*e0.y; acc.z += v[0]*e0.z; acc.w += v[0]*e0.w; }
        if (cnt > 1) { acc.x += v[1]*e1.x; acc.y += v[1]*e1.y; acc.z += v[1]*e1.z; acc.w += v[1]*e1.w; }
        if (cnt > 2) { acc.x += v[2]*e2.x; acc.y += v[2]*e2.y; acc.z += v[2]*e2.z; acc.w += v[2]*e2.w; }
        if (cnt > 3) { acc.x += v[3]*e3.x; acc.y += v[3]*e3.y; acc.z += v[3]*e3.z; acc.w += v[3]*e3.w; }

        ge += cnt;
        if (cnt < 4) break;
    }

    // Flush the final owned run (exclusive).
    st_feat<DST_H>(dp + (size_t)cur * DST_RB, acc);

    // If this run contained the globally last edge, zero all trailing rows.
    if (ge >= n_edges) {
        for (int rr = cur + 1; rr < n_rows; rr++)
            st_feat<DST_H>(dp + (size_t)rr * DST_RB, z4);
    }
}

extern "C" void kernel_launch(void* const* d_in, const int* in_sizes, int n_in,
                              void* d_out, int out_size) {
    const char*  x    = (const char*) d_in[0];
    const int*   erow = (const int*)  d_in[1];
    const int*   ecol = (const int*)  d_in[2];
    const float* eval = (const float*)d_in[3];
    char*        out  = (char*)d_out;

    const int n_edges = in_sizes[1];
    const int n_rows  = out_size / D_FEAT;

    void* tmp_sym = nullptr;
    cudaGetSymbolAddress(&tmp_sym, g_tmp);
    char* tmp = (char*)tmp_sym;

    const int sgrid = (n_edges + EPB - 1) / EPB;

    // Hop 1: tmp(fp16) = A @ x(fp32)
    spmm_kernel<false, true><<<sgrid, THREADS>>>(x, erow, ecol, eval, tmp,
                                                 n_edges, n_rows);
    // Hop 2: out(fp32) = A @ tmp(fp16)
    spmm_kernel<true, false><<<sgrid, THREADS>>>(tmp, erow, ecol, eval, out,
                                                 n_edges, n_rows);
}

// round 7
// speedup vs baseline: 1.3670x; 1.3670x over previous
#include <cuda_runtime.h>
#include <cuda_fp16.h>
#include <cstdint>

#define D_FEAT      64
#define N_NODES_MAX 100000
#define EPS         64            // edges per 16-thread group (R3-proven)
#define SUBS        8             // groups per block
#define EPB         (EPS * SUBS)  // 512 edges per block
#define THREADS     128

// Scratch (allocation-free). Intermediate hop in fp16.
__device__ __half g_tmp[(size_t)N_NODES_MAX * D_FEAT];

__device__ __forceinline__ void red_add_v4(float* p, float4 a) {
    asm volatile("red.global.add.v4.f32 [%0], {%1, %2, %3, %4};"
                 :: "l"(p), "f"(a.x), "f"(a.y), "f"(a.z), "f"(a.w)
                 : "memory");
}
__device__ __forceinline__ void red_add_h2(uint32_t* p, float2 v) {
    __half2 h = __float22half2_rn(v);
    asm volatile("red.global.add.noftz.f16x2 [%0], %1;"
                 :: "l"(p), "r"(*reinterpret_cast<uint32_t*>(&h))
                 : "memory");
}

// ---- per-dtype feature row helpers (each d4-thread owns 4 features) ----
template <bool HALF>
__device__ __forceinline__ float4 ld_feat(const char* p) {
    if (HALF) {
        uint2 r = *reinterpret_cast<const uint2*>(p);
        float2 a = __half22float2(*reinterpret_cast<__half2*>(&r.x));
        float2 b = __half22float2(*reinterpret_cast<__half2*>(&r.y));
        return make_float4(a.x, a.y, b.x, b.y);
    } else {
        return *reinterpret_cast<const float4*>(p);
    }
}
template <bool HALF>
__device__ __forceinline__ void st_feat(char* p, float4 v) {
    if (HALF) {
        uint2 u;
        __half2 h0 = __float22half2_rn(make_float2(v.x, v.y));
        __half2 h1 = __float22half2_rn(make_float2(v.z, v.w));
        u.x = *reinterpret_cast<uint32_t*>(&h0);
        u.y = *reinterpret_cast<uint32_t*>(&h1);
        *reinterpret_cast<uint2*>(p) = u;
    } else {
        *reinterpret_cast<float4*>(p) = v;
    }
}
template <bool HALF>
__device__ __forceinline__ void red_feat(char* p, float4 v) {
    if (HALF) {
        uint32_t* u = reinterpret_cast<uint32_t*>(p);
        red_add_h2(u + 0, make_float2(v.x, v.y));
        red_add_h2(u + 1, make_float2(v.z, v.w));
    } else {
        red_add_v4(reinterpret_cast<float*>(p), v);
    }
}

// Zero both hop buffers (tmp fp16 + out fp32). 512 threads, 2 float4 each.
__global__ void zero2_kernel(float4* __restrict__ t, int t4,
                             float4* __restrict__ o, int o4) {
    const float4 z = make_float4(0.f, 0.f, 0.f, 0.f);
    int i = (blockIdx.x * blockDim.x + threadIdx.x) * 2;
    if (i < t4)     t[i]     = z;
    if (i + 1 < t4) t[i + 1] = z;
    if (i < o4)     o[i]     = z;
    if (i + 1 < o4) o[i + 1] = z;
}

// R3-proven sorted-row SpMM: interior runs -> exclusive STG, boundary runs ->
// red.add into pre-zeroed dst. 8 gathers in flight per inner iteration.
template <bool SRC_H, bool DST_H>
__global__ void __launch_bounds__(THREADS)
spmm_kernel(const char* __restrict__ src,
            const int*  __restrict__ erow,
            const int*  __restrict__ ecol,
            const float* __restrict__ eval,
            char*       __restrict__ dst,
            int n_edges) {
    constexpr int SRC_RB = SRC_H ? 128 : 256;
    constexpr int DST_RB = DST_H ? 128 : 256;
    constexpr int SRC_TB = SRC_H ? 8 : 16;
    constexpr int DST_TB = DST_H ? 8 : 16;

    __shared__ alignas(16) int   s_row[EPB];
    __shared__ alignas(16) int   s_off[EPB];   // col * SRC_RB
    __shared__ alignas(16) float s_val[EPB];

    const int base = blockIdx.x * EPB;
    const int tid  = threadIdx.x;

    // Vectorized staging; pad with last valid row, val = 0.
    {
        const int i = tid * 4;
        const int e = base + i;
        if (e + 3 < n_edges) {
            int4   r = *reinterpret_cast<const int4*>(erow + e);
            int4   c = *reinterpret_cast<const int4*>(ecol + e);
            float4 v = *reinterpret_cast<const float4*>(eval + e);
            c.x *= SRC_RB; c.y *= SRC_RB; c.z *= SRC_RB; c.w *= SRC_RB;
            *reinterpret_cast<int4*>(s_row + i)   = r;
            *reinterpret_cast<int4*>(s_off + i)   = c;
            *reinterpret_cast<float4*>(s_val + i) = v;
        } else {
            #pragma unroll
            for (int k = 0; k < 4; k++) {
                int ee   = e + k;
                int esrc = min(ee, n_edges - 1);
                int in   = (ee < n_edges);
                s_row[i + k] = erow[esrc];
                s_off[i + k] = in ? ecol[esrc] * SRC_RB : 0;
                s_val[i + k] = in ? eval[esrc] : 0.f;
            }
        }
    }
    __syncthreads();

    const int d4  = tid & 15;
    const int sub = tid >> 4;
    const int off = sub * EPS;
    const char* sp = src + d4 * SRC_TB;
    char*       dp = dst + d4 * DST_TB;

    int    cur       = s_row[off];
    int    run_start = 0;
    float4 acc       = make_float4(0.f, 0.f, 0.f, 0.f);

    for (int ib = 0; ib < EPS; ib += 8) {
        const int4   ra = *reinterpret_cast<const int4*>(s_row + off + ib);
        const int4   rb = *reinterpret_cast<const int4*>(s_row + off + ib + 4);
        const int4   ca = *reinterpret_cast<const int4*>(s_off + off + ib);
        const int4   cb = *reinterpret_cast<const int4*>(s_off + off + ib + 4);
        const float4 va = *reinterpret_cast<const float4*>(s_val + off + ib);
        const float4 vb = *reinterpret_cast<const float4*>(s_val + off + ib + 4);

        // 8 gathers in flight (MLP = 8)
        const float4 g0 = ld_feat<SRC_H>(sp + ca.x);
        const float4 g1 = ld_feat<SRC_H>(sp + ca.y);
        const float4 g2 = ld_feat<SRC_H>(sp + ca.z);
        const float4 g3 = ld_feat<SRC_H>(sp + ca.w);
        const float4 g4 = ld_feat<SRC_H>(sp + cb.x);
        const float4 g5 = ld_feat<SRC_H>(sp + cb.y);
        const float4 g6 = ld_feat<SRC_H>(sp + cb.z);
        const float4 g7 = ld_feat<SRC_H>(sp + cb.w);

        #define STEP(R, V, G, IDX)                                           \
        do {                                                                 \
            if ((R) != cur) {                                                \
                char* p = dp + (size_t)cur * DST_RB;                         \
                if (run_start > 0) {                                         \
                    st_feat<DST_H>(p, acc);       /* exclusive interior */   \
                } else {                                                     \
                    red_feat<DST_H>(p, acc);      /* boundary */             \
                }                                                            \
                acc = make_float4(0.f, 0.f, 0.f, 0.f);                       \
                cur = (R);                                                   \
                run_start = (IDX);                                           \
            }                                                                \
            acc.x += (V) * (G).x;                                            \
            acc.y += (V) * (G).y;                                            \
            acc.z += (V) * (G).z;                                            \
            acc.w += (V) * (G).w;                                            \
        } while (0)

        STEP(ra.x, va.x, g0, ib + 0);
        STEP(ra.y, va.y, g1, ib + 1);
        STEP(ra.z, va.z, g2, ib + 2);
        STEP(ra.w, va.w, g3, ib + 3);
        STEP(rb.x, vb.x, g4, ib + 4);
        STEP(rb.y, vb.y, g5, ib + 5);
        STEP(rb.z, vb.z, g6, ib + 6);
        STEP(rb.w, vb.w, g7, ib + 7);
        #undef STEP
    }

    // Final run may continue into the next group -> always atomic.
    red_feat<DST_H>(dp + (size_t)cur * DST_RB, acc);
}

extern "C" void kernel_launch(void* const* d_in, const int* in_sizes, int n_in,
                              void* d_out, int out_size) {
    const char*  x    = (const char*) d_in[0];
    const int*   erow = (const int*)  d_in[1];
    const int*   ecol = (const int*)  d_in[2];
    const float* eval = (const float*)d_in[3];
    char*        out  = (char*)d_out;

    const int n_edges = in_sizes[1];
    const int n_rows  = out_size / D_FEAT;

    void* tmp_sym = nullptr;
    cudaGetSymbolAddress(&tmp_sym, g_tmp);
    char* tmp = (char*)tmp_sym;

    const int t4 = n_rows * D_FEAT * 2 / 16;   // fp16 tmp, float4 units
    const int o4 = n_rows * D_FEAT * 4 / 16;   // fp32 out, float4 units
    const int zn = (o4 + 1) / 2;               // 2 float4 per thread per buffer
    const int zgrid = (zn + 511) / 512;
    const int sgrid = (n_edges + EPB - 1) / EPB;

    zero2_kernel<<<zgrid, 512>>>((float4*)tmp, t4, (float4*)out, o4);

    // Hop 1: tmp(fp16) = A @ x(fp32)
    spmm_kernel<false, true><<<sgrid, THREADS>>>(x, erow, ecol, eval, tmp, n_edges);
    // Hop 2: out(fp32) = A @ tmp(fp16)
    spmm_kernel<true, false><<<sgrid, THREADS>>>(tmp, erow, ecol, eval, out, n_edges);
}